// round 13
// baseline (speedup 1.0000x reference)
#include <cuda_runtime.h>
#include <cuda_fp16.h>
#include <cstdint>
#include <cstring>

// ---------------------------------------------------------------------------
// Problem constants
// ---------------------------------------------------------------------------
#define BATCH 4
#define LTOT  13294
#define MROWS (BATCH * LTOT)   // 53176
#define DMODEL 256
#define DFFN   1024
#define NHEAD  8
#define NLVL   4
#define NPTS   4
#define DHEAD  32

// ---------------------------------------------------------------------------
// Scratch (device globals)
// ---------------------------------------------------------------------------
__device__ __half g_src_h[MROWS * DMODEL];
__device__ __half g_q_h  [MROWS * DMODEL];
__device__ __half g_v_h  [MROWS * DMODEL];
__device__ float  g_oa   [MROWS * 384];     // offsets(256) + attn logits(128), f32
__device__ __half g_samp_h[MROWS * DMODEL];
__device__ float  g_tmp  [MROWS * DMODEL];
__device__ float  g_x    [MROWS * DMODEL];
__device__ __half g_x_h  [MROWS * DMODEL];
__device__ __half g_h1_h [MROWS * DFFN];
// transposed weights [N, K] fp16
__device__ __half g_wt_val[DMODEL * DMODEL];
__device__ __half g_wt_oa [384 * DMODEL];
__device__ __half g_wt_out[DMODEL * DMODEL];
__device__ __half g_wt_1  [DFFN * DMODEL];
__device__ __half g_wt_2  [DMODEL * DFFN];
__device__ float  g_bias_oa[384];

// ---------------------------------------------------------------------------
// Helpers
// ---------------------------------------------------------------------------
__device__ __forceinline__ uint32_t h2u(__half2 v) {
    uint32_t r;
    memcpy(&r, &v, 4);
    return r;
}

__device__ __forceinline__ void mma_16n8k16(float* d, const uint32_t* a, const uint32_t* b) {
    asm volatile(
        "mma.sync.aligned.m16n8k16.row.col.f32.f16.f16.f32 "
        "{%0,%1,%2,%3}, {%4,%5,%6,%7}, {%8,%9}, {%0,%1,%2,%3};"
        : "+f"(d[0]), "+f"(d[1]), "+f"(d[2]), "+f"(d[3])
        : "r"(a[0]), "r"(a[1]), "r"(a[2]), "r"(a[3]), "r"(b[0]), "r"(b[1]));
}

#define LDSM_X4(r0, r1, r2, r3, addr) \
    asm volatile("ldmatrix.sync.aligned.m8n8.x4.shared.b16 {%0,%1,%2,%3}, [%4];" \
        : "=r"(r0), "=r"(r1), "=r"(r2), "=r"(r3) : "r"(addr))

#define CP_ASYNC16(dst, src, nbytes) \
    asm volatile("cp.async.cg.shared.global [%0], [%1], 16, %2;" \
        :: "r"(dst), "l"(src), "r"(nbytes))
#define CP_COMMIT() asm volatile("cp.async.commit_group;")
#define CP_WAIT2()  asm volatile("cp.async.wait_group 2;")
#define CP_WAIT1()  asm volatile("cp.async.wait_group 1;")
#define CP_WAIT0()  asm volatile("cp.async.wait_group 0;")

// ---------------------------------------------------------------------------
// fp16 mma.sync GEMM, 4-stage cp.async pipeline, ldmatrix fragment loads.
// C[M,N] = A[M,K] @ Wt[N,K]^T + bias (+relu | +res)
// 128x128 CTA tile, BK=32 (fp16), 8 warps of 32x64, m16n8k16.
// MODE: 0 = bias, 1 = bias+relu, 2 = bias+residual(f32)
// OUTH: 0 = f32 output, 1 = fp16 output
// ---------------------------------------------------------------------------
#define LDSH 40                          // padded smem row stride (halfs) = 80B
#define TILE_H (128 * LDSH)              // halfs per tile buffer
#define TILE_BYTES (TILE_H * 2)          // 10240
#define NSTAGE 4
#define GEMM_SMEM (2 * NSTAGE * TILE_BYTES)  // 81920 bytes (A0..3, B0..3)

template <int MODE, int OUTH>
__global__ __launch_bounds__(256)
void gemm_mma(const __half* __restrict__ A, const __half* __restrict__ Wt,
              const float* __restrict__ bias, const float* __restrict__ res,
              void* __restrict__ Cv, int M, int N, int K) {
    extern __shared__ __half smem[];
    __half* sAbase = smem;                      // NSTAGE tiles
    __half* sBbase = smem + NSTAGE * TILE_H;    // NSTAGE tiles

    const int tid  = threadIdx.x;
    const int wid  = tid >> 5;
    const int lane = tid & 31;
    const int g    = lane >> 2;      // groupID 0..7
    const int tig  = lane & 3;       // thread-in-group 0..3
    const int wm   = wid >> 1;       // 0..3 (32-row slab)
    const int wn   = wid & 1;        // 0..1 (64-col slab)
    const int brow = blockIdx.y * 128;
    const int bcol = blockIdx.x * 128;
    const int NC   = K >> 5;

    // cp.async loader: 2 segments per thread per matrix (512 x 16B per tile)
    const int r0l = tid >> 2;          // rows 0..63
    const int seg = tid & 3;           // 16B segment within 64B row
    uint32_t cpA[2], cpB[2];
#pragma unroll
    for (int i = 0; i < 2; i++) {
        cpA[i] = (uint32_t)__cvta_generic_to_shared(&sAbase[(r0l + i * 64) * LDSH + seg * 8]);
        cpB[i] = (uint32_t)__cvta_generic_to_shared(&sBbase[(r0l + i * 64) * LDSH + seg * 8]);
    }

    // ldmatrix offsets (bytes, relative to tile base; +32B per k-step of 16)
    uint32_t aAddr0 = (uint32_t)__cvta_generic_to_shared(sAbase);
    uint32_t bAddr0 = (uint32_t)__cvta_generic_to_shared(sBbase);
    uint32_t aoff[2];
#pragma unroll
    for (int i = 0; i < 2; i++)
        aoff[i] = (uint32_t)(((wm * 32 + i * 16 + (lane & 15)) * LDSH + ((lane >> 4) << 3)) * 2);
    uint32_t boff[4];
#pragma unroll
    for (int j4 = 0; j4 < 4; j4++)
        boff[j4] = (uint32_t)(((wn * 64 + j4 * 16 + (lane & 7) + ((lane >> 4) << 3)) * LDSH
                               + (((lane >> 3) & 1) << 3)) * 2);

    float acc[2][8][4];
#pragma unroll
    for (int i = 0; i < 2; i++)
#pragma unroll
        for (int j = 0; j < 8; j++)
#pragma unroll
            for (int t = 0; t < 4; t++) acc[i][j][t] = 0.f;

    auto issue = [&](int ck) {
        const uint32_t bo = (uint32_t)(ck % NSTAGE) * TILE_BYTES;
        const int k0 = ck << 5;
#pragma unroll
        for (int i = 0; i < 2; i++) {
            int row = r0l + i * 64;
            CP_ASYNC16(cpA[i] + bo, &A[(size_t)(brow + row) * K + k0 + seg * 8],
                       (brow + row < M) ? 16 : 0);
            CP_ASYNC16(cpB[i] + bo, &Wt[(size_t)(bcol + row) * K + k0 + seg * 8], 16);
        }
        CP_COMMIT();
    };

    issue(0);
    if (NC > 1) issue(1);
    if (NC > 2) issue(2);
    for (int c = 0; c < NC; ++c) {
        // chunk c must be complete; pending allowed = min(2, NC-1-c)
        if (c + 3 <= NC)      CP_WAIT2();
        else if (c + 2 == NC) CP_WAIT1();
        else                  CP_WAIT0();
        __syncthreads();
        if (c + 3 < NC) issue(c + 3);

        const uint32_t tb = (uint32_t)(c % NSTAGE) * TILE_BYTES;
        const uint32_t aB = aAddr0 + tb;
        const uint32_t bB = bAddr0 + tb;
#pragma unroll
        for (int s = 0; s < 2; s++) {           // two K=16 steps per chunk
            const uint32_t ks = (uint32_t)(s * 32);  // 16 halfs = 32B
            uint32_t afr[2][4];
#pragma unroll
            for (int i = 0; i < 2; i++)
                LDSM_X4(afr[i][0], afr[i][1], afr[i][2], afr[i][3], aB + aoff[i] + ks);
#pragma unroll
            for (int j4 = 0; j4 < 4; j4++) {
                uint32_t b0[2], b1[2];
                LDSM_X4(b0[0], b0[1], b1[0], b1[1], bB + boff[j4] + ks);
                mma_16n8k16(acc[0][2 * j4 + 0], afr[0], b0);
                mma_16n8k16(acc[1][2 * j4 + 0], afr[1], b0);
                mma_16n8k16(acc[0][2 * j4 + 1], afr[0], b1);
                mma_16n8k16(acc[1][2 * j4 + 1], afr[1], b1);
            }
        }
    }

    // epilogue
    float* Cf = (float*)Cv;
    __half* Ch = (__half*)Cv;
#pragma unroll
    for (int i = 0; i < 2; i++) {
        int r0 = brow + wm * 32 + i * 16 + g;
#pragma unroll
        for (int j = 0; j < 8; j++) {
            int col = bcol + wn * 64 + j * 8 + 2 * tig;
            float b0 = __ldg(&bias[col]);
            float b1 = __ldg(&bias[col + 1]);
#pragma unroll
            for (int half_ = 0; half_ < 2; half_++) {
                int r = r0 + half_ * 8;
                if (r >= M) continue;
                float v0 = acc[i][j][2 * half_ + 0] + b0;
                float v1 = acc[i][j][2 * half_ + 1] + b1;
                if (MODE == 1) { v0 = fmaxf(v0, 0.f); v1 = fmaxf(v1, 0.f); }
                if (MODE == 2) {
                    const float2 rr = *reinterpret_cast<const float2*>(&res[(size_t)r * N + col]);
                    v0 += rr.x; v1 += rr.y;
                }
                if (OUTH) {
                    __half2 hv = __floats2half2_rn(v0, v1);
                    *reinterpret_cast<uint32_t*>(&Ch[(size_t)r * N + col]) = h2u(hv);
                } else {
                    *reinterpret_cast<float2*>(&Cf[(size_t)r * N + col]) = make_float2(v0, v1);
                }
            }
        }
    }
}

// ---------------------------------------------------------------------------
// Merged weight prep (one launch): all transposes -> fp16 [N,K] + bias concat.
// grid: [0,224) small W tiles | 224 bias | [225,481) W1 | [481,737) W2
// ---------------------------------------------------------------------------
__global__ void prep_weights_k(const float* __restrict__ Wval, const float* __restrict__ Woff,
                               const float* __restrict__ Wattn, const float* __restrict__ Wout,
                               const float* __restrict__ W1, const float* __restrict__ W2,
                               const float* __restrict__ boff, const float* __restrict__ battn,
                               __half* __restrict__ wtv, __half* __restrict__ wtoa,
                               __half* __restrict__ wtO, __half* __restrict__ wt1,
                               __half* __restrict__ wt2, float* __restrict__ bias_oa) {
    __shared__ float t[32][33];
    int blk = blockIdx.x;
    int x = threadIdx.x, y = threadIdx.y;
    if (blk == 224) {
        int tt = y * 32 + x;
        for (int i = tt; i < 384; i += 256)
            bias_oa[i] = (i < 256) ? boff[i] : battn[i - 256];
        return;
    }
    const float* W; __half* Wt; int K, N, lb;
    if (blk < 64)       { W = Wval;  Wt = wtv;              K = 256;  N = 256;  lb = blk; }
    else if (blk < 128) { W = Woff;  Wt = wtoa;             K = 256;  N = 256;  lb = blk - 64; }
    else if (blk < 160) { W = Wattn; Wt = wtoa + 256 * 256; K = 256;  N = 128;  lb = blk - 128; }
    else if (blk < 224) { W = Wout;  Wt = wtO;              K = 256;  N = 256;  lb = blk - 160; }
    else if (blk < 481) { W = W1;    Wt = wt1;              K = 256;  N = 1024; lb = blk - 225; }
    else                { W = W2;    Wt = wt2;              K = 1024; N = 256;  lb = blk - 481; }
    int ntx = N >> 5;
    int n0 = (lb % ntx) * 32, k0 = (lb / ntx) * 32;
#pragma unroll
    for (int i = 0; i < 32; i += 8)
        t[y + i][x] = W[(size_t)(k0 + y + i) * N + n0 + x];
    __syncthreads();
#pragma unroll
    for (int i = 0; i < 32; i += 8)
        Wt[(size_t)(n0 + y + i) * K + k0 + x] = __float2half(t[x][y + i]);
}

// ---------------------------------------------------------------------------
// add: q_h = h(src+pos); src_h = h(src)
// ---------------------------------------------------------------------------
__global__ void add_k(const float4* __restrict__ src4, const float4* __restrict__ pos4,
                      __half* __restrict__ qh, __half* __restrict__ srch, int n4) {
    int i = blockIdx.x * blockDim.x + threadIdx.x;
    if (i >= n4) return;
    float4 s = src4[i], p = pos4[i];
    __half2 q0 = __floats2half2_rn(s.x + p.x, s.y + p.y);
    __half2 q1 = __floats2half2_rn(s.z + p.z, s.w + p.w);
    __half2 s0 = __floats2half2_rn(s.x, s.y);
    __half2 s1 = __floats2half2_rn(s.z, s.w);
    *reinterpret_cast<uint2*>(&qh[(size_t)i * 4])   = make_uint2(h2u(q0), h2u(q1));
    *reinterpret_cast<uint2*>(&srch[(size_t)i * 4]) = make_uint2(h2u(s0), h2u(s1));
}

// ---------------------------------------------------------------------------
// Deformable sampling (fp16 v): one warp per (b,q, head-pair).
// lane = h2(1b) | p(2b) | c8(2b): 2 heads x 4 points x 4 channel-octets.
// Fused softmax over 16 (level,point) logits per head via shuffles.
// ---------------------------------------------------------------------------
__global__ __launch_bounds__(256)
void sample_k(const __half* __restrict__ v, const float* __restrict__ oa,
              const float* __restrict__ ref, __half* __restrict__ out) {
    int warp = (blockIdx.x * blockDim.x + threadIdx.x) >> 5;
    int lane = threadIdx.x & 31;
    if (warp >= MROWS * 4) return;
    int hp  = warp & 3;
    int row = warp >> 2;
    int b   = row / LTOT;
    int h2i = lane >> 4;         // head within pair
    int p   = (lane >> 2) & 3;   // point
    int c8  = lane & 3;          // channel octet (8 halfs)
    int h   = hp * 2 + h2i;

    const int HS[4] = {100, 50, 25, 13};
    const int ST[4] = {0, 10000, 12500, 13125};

    const float* offp = oa + (size_t)row * 384 + h * 32;
    const float* lgp  = oa + (size_t)row * 384 + 256 + h * 16;
    const float* refp = ref + (size_t)row * 8;

    float lg[4];
#pragma unroll
    for (int l = 0; l < 4; l++) lg[l] = __ldg(lgp + l * 4 + p);
    float mx = fmaxf(fmaxf(lg[0], lg[1]), fmaxf(lg[2], lg[3]));
    mx = fmaxf(mx, __shfl_xor_sync(0xffffffffu, mx, 4));
    mx = fmaxf(mx, __shfl_xor_sync(0xffffffffu, mx, 8));
    float e[4], s = 0.f;
#pragma unroll
    for (int l = 0; l < 4; l++) { e[l] = __expf(lg[l] - mx); s += e[l]; }
    s += __shfl_xor_sync(0xffffffffu, s, 4);
    s += __shfl_xor_sync(0xffffffffu, s, 8);
    const float inv = 1.f / s;

    float acc[8];
#pragma unroll
    for (int j = 0; j < 8; j++) acc[j] = 0.f;

#pragma unroll
    for (int l = 0; l < 4; l++) {
        const int H = HS[l], W = HS[l], S = ST[l];
        float rx = __ldg(refp + l * 2 + 0);
        float ry = __ldg(refp + l * 2 + 1);
        float ox = __ldg(offp + l * 8 + p * 2 + 0);
        float oy = __ldg(offp + l * 8 + p * 2 + 1);
        float aww = e[l] * inv;
        float x = rx * (float)W + ox - 0.5f;
        float y = ry * (float)H + oy - 0.5f;
        float x0f = floorf(x), y0f = floorf(y);
        float lx = x - x0f, ly = y - y0f;
        int x0 = (int)x0f, y0 = (int)y0f;
        float w00 = (1.f - lx) * (1.f - ly) * aww;
        float w10 = lx * (1.f - ly) * aww;
        float w01 = (1.f - lx) * ly * aww;
        float w11 = lx * ly * aww;
        bool vx0 = (x0 >= 0) && (x0 < W);
        bool vx1 = (x0 + 1 >= 0) && (x0 + 1 < W);
        bool vy0 = (y0 >= 0) && (y0 < H);
        bool vy1 = (y0 + 1 >= 0) && (y0 + 1 < H);
        // uint4 gather: 8 halfs. index stride = 32 uint4 per spatial pos.
        const uint4* vb = reinterpret_cast<const uint4*>(
            v + (size_t)(b * LTOT + S) * 256) + h * 4 + c8;
#define TAP(widx, cond, wv)                                                   \
        if (cond) {                                                           \
            uint4 t = __ldg(vb + (size_t)(widx) * 32);                        \
            __half2 hh[4];                                                    \
            memcpy(hh, &t, 16);                                               \
            _Pragma("unroll")                                                 \
            for (int j = 0; j < 4; j++) {                                     \
                float2 f = __half22float2(hh[j]);                             \
                acc[2 * j]     += (wv) * f.x;                                 \
                acc[2 * j + 1] += (wv) * f.y;                                 \
            }                                                                 \
        }
        TAP(y0 * W + x0,           vy0 && vx0, w00)
        TAP(y0 * W + x0 + 1,       vy0 && vx1, w10)
        TAP((y0 + 1) * W + x0,     vy1 && vx0, w01)
        TAP((y0 + 1) * W + x0 + 1, vy1 && vx1, w11)
#undef TAP
    }
    // reduce over point (lane bits 2,3)
#pragma unroll
    for (int j = 0; j < 8; j++) {
        acc[j] += __shfl_xor_sync(0xffffffffu, acc[j], 4);
        acc[j] += __shfl_xor_sync(0xffffffffu, acc[j], 8);
    }
    if (p == 0) {
        uint4 pk = make_uint4(h2u(__floats2half2_rn(acc[0], acc[1])),
                              h2u(__floats2half2_rn(acc[2], acc[3])),
                              h2u(__floats2half2_rn(acc[4], acc[5])),
                              h2u(__floats2half2_rn(acc[6], acc[7])));
        *reinterpret_cast<uint4*>(&out[(size_t)row * DMODEL + h * DHEAD + c8 * 8]) = pk;
    }
}

// ---------------------------------------------------------------------------
// LayerNorm over 256; optional fp16 copy
// ---------------------------------------------------------------------------
__global__ __launch_bounds__(256)
void ln_k(const float* __restrict__ in, const float* __restrict__ g,
          const float* __restrict__ b, float* __restrict__ out,
          __half* __restrict__ out_h) {
    int row = blockIdx.x;
    int t = threadIdx.x;
    float v = in[(size_t)row * DMODEL + t];
    float s = v, s2 = v * v;
#pragma unroll
    for (int o = 16; o > 0; o >>= 1) {
        s  += __shfl_xor_sync(0xffffffff, s,  o);
        s2 += __shfl_xor_sync(0xffffffff, s2, o);
    }
    __shared__ float sh[8], sh2[8];
    int wid = t >> 5, lane = t & 31;
    if (lane == 0) { sh[wid] = s; sh2[wid] = s2; }
    __syncthreads();
    float ts = 0.f, ts2 = 0.f;
#pragma unroll
    for (int i = 0; i < 8; i++) { ts += sh[i]; ts2 += sh2[i]; }
    float mu = ts * (1.f / DMODEL);
    float var = ts2 * (1.f / DMODEL) - mu * mu;
    float inv = rsqrtf(var + 1e-5f);
    float r = (v - mu) * inv * g[t] + b[t];
    out[(size_t)row * DMODEL + t] = r;
    if (out_h) out_h[(size_t)row * DMODEL + t] = __float2half(r);
}

// ---------------------------------------------------------------------------
// Launch
// ---------------------------------------------------------------------------
extern "C" void kernel_launch(void* const* d_in, const int* in_sizes, int n_in,
                              void* d_out, int out_size) {
    const float* src   = (const float*)d_in[0];
    const float* pos   = (const float*)d_in[1];
    const float* ref   = (const float*)d_in[2];
    const float* Woff  = (const float*)d_in[5];
    const float* boff  = (const float*)d_in[6];
    const float* Wattn = (const float*)d_in[7];
    const float* battn = (const float*)d_in[8];
    const float* Wval  = (const float*)d_in[9];
    const float* bval  = (const float*)d_in[10];
    const float* Wout  = (const float*)d_in[11];
    const float* bout  = (const float*)d_in[12];
    const float* lsg   = (const float*)d_in[13];
    const float* lsb   = (const float*)d_in[14];
    const float* W1    = (const float*)d_in[15];
    const float* b1    = (const float*)d_in[16];
    const float* W2    = (const float*)d_in[17];
    const float* b2    = (const float*)d_in[18];
    const float* lfg   = (const float*)d_in[19];
    const float* lfb   = (const float*)d_in[20];
    float* out = (float*)d_out;

    __half *srch, *qh, *vh, *samph, *xh, *h1h;
    __half *wtv, *wtoa, *wtO, *wt1, *wt2;
    float *oa, *tmp, *x, *boa;
    cudaGetSymbolAddress((void**)&srch,  g_src_h);
    cudaGetSymbolAddress((void**)&qh,    g_q_h);
    cudaGetSymbolAddress((void**)&vh,    g_v_h);
    cudaGetSymbolAddress((void**)&oa,    g_oa);
    cudaGetSymbolAddress((void**)&samph, g_samp_h);
    cudaGetSymbolAddress((void**)&tmp,   g_tmp);
    cudaGetSymbolAddress((void**)&x,     g_x);
    cudaGetSymbolAddress((void**)&xh,    g_x_h);
    cudaGetSymbolAddress((void**)&h1h,   g_h1_h);
    cudaGetSymbolAddress((void**)&wtv,   g_wt_val);
    cudaGetSymbolAddress((void**)&wtoa,  g_wt_oa);
    cudaGetSymbolAddress((void**)&wtO,   g_wt_out);
    cudaGetSymbolAddress((void**)&wt1,   g_wt_1);
    cudaGetSymbolAddress((void**)&wt2,   g_wt_2);
    cudaGetSymbolAddress((void**)&boa,   g_bias_oa);

    cudaFuncSetAttribute(gemm_mma<0,0>, cudaFuncAttributeMaxDynamicSharedMemorySize, GEMM_SMEM);
    cudaFuncSetAttribute(gemm_mma<0,1>, cudaFuncAttributeMaxDynamicSharedMemorySize, GEMM_SMEM);
    cudaFuncSetAttribute(gemm_mma<1,1>, cudaFuncAttributeMaxDynamicSharedMemorySize, GEMM_SMEM);
    cudaFuncSetAttribute(gemm_mma<2,0>, cudaFuncAttributeMaxDynamicSharedMemorySize, GEMM_SMEM);

    const int M = MROWS;
    const int mblk = (M + 127) / 128;   // 416
    dim3 tb(32, 8);

    // 1. all weight transposes + bias concat in ONE launch
    prep_weights_k<<<737, tb>>>(Wval, Woff, Wattn, Wout, W1, W2, boff, battn,
                                wtv, wtoa, wtO, wt1, wt2, boa);
    // 2. q_h = h(src+pos); src_h = h(src)
    {
        int n4 = M * DMODEL / 4;
        add_k<<<(n4 + 255) / 256, 256>>>((const float4*)src, (const float4*)pos,
                                         qh, srch, n4);
    }
    // 3. v_h = h(src_h @ Wval + bval)
    gemm_mma<0,1><<<dim3(2, mblk), 256, GEMM_SMEM>>>(srch, wtv, bval, nullptr, vh, M, 256, 256);
    // 4. oa = q_h @ [Woff|Wattn] + [boff|battn]  (f32 out)
    gemm_mma<0,0><<<dim3(3, mblk), 256, GEMM_SMEM>>>(qh, wtoa, boa, nullptr, oa, M, 384, 256);
    // 5. sampling + fused softmax -> samp_h
    sample_k<<<(M * 4 + 7) / 8, 256>>>(vh, oa, ref, samph);
    // 6. tmp = samp_h @ Wout + bout + src (f32)
    gemm_mma<2,0><<<dim3(2, mblk), 256, GEMM_SMEM>>>(samph, wtO, bout, src, tmp, M, 256, 256);
    // 7. x = LN(tmp), x_h copy
    ln_k<<<M, 256>>>(tmp, lsg, lsb, x, xh);
    // 8. h1_h = relu(x_h @ W1 + b1)  (fp16 out)
    gemm_mma<1,1><<<dim3(8, mblk), 256, GEMM_SMEM>>>(xh, wt1, b1, nullptr, h1h, M, 1024, 256);
    // 9. tmp = h1_h @ W2 + b2 + x  (f32)
    gemm_mma<2,0><<<dim3(2, mblk), 256, GEMM_SMEM>>>(h1h, wt2, b2, x, tmp, M, 256, 1024);
    // 10. out = LN(tmp)
    ln_k<<<M, 256>>>(tmp, lfg, lfb, out, nullptr);
}

// round 15
// speedup vs baseline: 1.4798x; 1.4798x over previous
#include <cuda_runtime.h>
#include <cuda_fp16.h>
#include <cstdint>
#include <cstring>

// ---------------------------------------------------------------------------
// Problem constants
// ---------------------------------------------------------------------------
#define BATCH 4
#define LTOT  13294
#define MROWS (BATCH * LTOT)   // 53176
#define DMODEL 256
#define DFFN   1024
#define NHEAD  8
#define NLVL   4
#define NPTS   4
#define DHEAD  32

// ---------------------------------------------------------------------------
// Scratch (device globals)
// ---------------------------------------------------------------------------
__device__ __half g_src_h[MROWS * DMODEL];
__device__ __half g_q_h  [MROWS * DMODEL];
__device__ __half g_v_h  [MROWS * DMODEL];
__device__ float  g_oa   [MROWS * 384];     // offsets(256) + attn logits(128), f32
__device__ __half g_samp_h[MROWS * DMODEL];
__device__ float  g_tmp  [MROWS * DMODEL];
__device__ float  g_x    [MROWS * DMODEL];
__device__ __half g_x_h  [MROWS * DMODEL];
__device__ __half g_h1_h [MROWS * DFFN];
// transposed weights [N, K] fp16
__device__ __half g_wt_val[DMODEL * DMODEL];
__device__ __half g_wt_oa [384 * DMODEL];
__device__ __half g_wt_out[DMODEL * DMODEL];
__device__ __half g_wt_1  [DFFN * DMODEL];
__device__ __half g_wt_2  [DMODEL * DFFN];
__device__ float  g_bias_oa[384];

// ---------------------------------------------------------------------------
// Helpers
// ---------------------------------------------------------------------------
__device__ __forceinline__ uint32_t h2u(__half2 v) {
    uint32_t r;
    memcpy(&r, &v, 4);
    return r;
}

__device__ __forceinline__ void mma_16n8k16(float* d, const uint32_t* a, const uint32_t* b) {
    asm volatile(
        "mma.sync.aligned.m16n8k16.row.col.f32.f16.f16.f32 "
        "{%0,%1,%2,%3}, {%4,%5,%6,%7}, {%8,%9}, {%0,%1,%2,%3};"
        : "+f"(d[0]), "+f"(d[1]), "+f"(d[2]), "+f"(d[3])
        : "r"(a[0]), "r"(a[1]), "r"(a[2]), "r"(a[3]), "r"(b[0]), "r"(b[1]));
}

#define LDSM_X4(r0, r1, r2, r3, addr) \
    asm volatile("ldmatrix.sync.aligned.m8n8.x4.shared.b16 {%0,%1,%2,%3}, [%4];" \
        : "=r"(r0), "=r"(r1), "=r"(r2), "=r"(r3) : "r"(addr))

#define CP_ASYNC16(dst, src, nbytes) \
    asm volatile("cp.async.cg.shared.global [%0], [%1], 16, %2;" \
        :: "r"(dst), "l"(src), "r"(nbytes))
#define CP_COMMIT() asm volatile("cp.async.commit_group;")
#define CP_WAIT1()  asm volatile("cp.async.wait_group 1;")
#define CP_WAIT0()  asm volatile("cp.async.wait_group 0;")

// ---------------------------------------------------------------------------
// fp16 mma.sync GEMM body (R10 config: 3-stage cp.async, ldmatrix, BK=32).
// 128x128 CTA tile, 8 warps of 32x64, m16n8k16.
// MODE: 0 = bias, 1 = bias+relu, 2 = bias+residual(f32)
// outh (runtime, constant-folded at compile-time call sites): fp16 vs f32 out
// ---------------------------------------------------------------------------
#define LDSH 40                          // padded smem row stride (halfs) = 80B
#define TILE_H (128 * LDSH)              // halfs per tile buffer
#define TILE_BYTES (TILE_H * 2)          // 10240
#define GEMM_SMEM (6 * TILE_BYTES)       // 61440 bytes (A0..2, B0..2)

template <int MODE>
__device__ __forceinline__
void gemm_body(const __half* __restrict__ A, const __half* __restrict__ Wt,
               const float* __restrict__ bias, const float* __restrict__ res,
               void* __restrict__ Cv, int M, int N, int K,
               bool outh, int brow, int bcol, __half* smem) {
    __half* sAbase = smem;                 // 3 tiles
    __half* sBbase = smem + 3 * TILE_H;    // 3 tiles

    const int tid  = threadIdx.x;
    const int wid  = tid >> 5;
    const int lane = tid & 31;
    const int g    = lane >> 2;      // groupID 0..7
    const int tig  = lane & 3;       // thread-in-group 0..3
    const int wm   = wid >> 1;       // 0..3 (32-row slab)
    const int wn   = wid & 1;        // 0..1 (64-col slab)
    const int NC   = K >> 5;

    // cp.async loader: 2 segments per thread per matrix (512 x 16B per tile)
    const int r0l = tid >> 2;          // rows 0..63
    const int seg = tid & 3;           // 16B segment within 64B row
    uint32_t cpA[2], cpB[2];
#pragma unroll
    for (int i = 0; i < 2; i++) {
        cpA[i] = (uint32_t)__cvta_generic_to_shared(&sAbase[(r0l + i * 64) * LDSH + seg * 8]);
        cpB[i] = (uint32_t)__cvta_generic_to_shared(&sBbase[(r0l + i * 64) * LDSH + seg * 8]);
    }

    // ldmatrix offsets (bytes, relative to tile base; +32B per k-step of 16)
    uint32_t aAddr0 = (uint32_t)__cvta_generic_to_shared(sAbase);
    uint32_t bAddr0 = (uint32_t)__cvta_generic_to_shared(sBbase);
    uint32_t aoff[2];
#pragma unroll
    for (int i = 0; i < 2; i++)
        aoff[i] = (uint32_t)(((wm * 32 + i * 16 + (lane & 15)) * LDSH + ((lane >> 4) << 3)) * 2);
    uint32_t boff[4];
#pragma unroll
    for (int j4 = 0; j4 < 4; j4++)
        boff[j4] = (uint32_t)(((wn * 64 + j4 * 16 + (lane & 7) + ((lane >> 4) << 3)) * LDSH
                               + (((lane >> 3) & 1) << 3)) * 2);

    float acc[2][8][4];
#pragma unroll
    for (int i = 0; i < 2; i++)
#pragma unroll
        for (int j = 0; j < 8; j++)
#pragma unroll
            for (int t = 0; t < 4; t++) acc[i][j][t] = 0.f;

    auto issue = [&](int ck) {
        const uint32_t bo = (uint32_t)(ck % 3) * TILE_BYTES;
        const int k0 = ck << 5;
#pragma unroll
        for (int i = 0; i < 2; i++) {
            int row = r0l + i * 64;
            CP_ASYNC16(cpA[i] + bo, &A[(size_t)(brow + row) * K + k0 + seg * 8],
                       (brow + row < M) ? 16 : 0);
            CP_ASYNC16(cpB[i] + bo, &Wt[(size_t)(bcol + row) * K + k0 + seg * 8], 16);
        }
        CP_COMMIT();
    };

    issue(0);
    if (NC > 1) issue(1);
    for (int c = 0; c < NC; ++c) {
        if (c + 1 < NC) CP_WAIT1(); else CP_WAIT0();
        __syncthreads();
        if (c + 2 < NC) issue(c + 2);

        const uint32_t tb = (uint32_t)(c % 3) * TILE_BYTES;
        const uint32_t aB = aAddr0 + tb;
        const uint32_t bB = bAddr0 + tb;
#pragma unroll
        for (int s = 0; s < 2; s++) {           // two K=16 steps per chunk
            const uint32_t ks = (uint32_t)(s * 32);  // 16 halfs = 32B
            uint32_t afr[2][4];
#pragma unroll
            for (int i = 0; i < 2; i++)
                LDSM_X4(afr[i][0], afr[i][1], afr[i][2], afr[i][3], aB + aoff[i] + ks);
#pragma unroll
            for (int j4 = 0; j4 < 4; j4++) {
                uint32_t b0[2], b1[2];
                LDSM_X4(b0[0], b0[1], b1[0], b1[1], bB + boff[j4] + ks);
                mma_16n8k16(acc[0][2 * j4 + 0], afr[0], b0);
                mma_16n8k16(acc[1][2 * j4 + 0], afr[1], b0);
                mma_16n8k16(acc[0][2 * j4 + 1], afr[0], b1);
                mma_16n8k16(acc[1][2 * j4 + 1], afr[1], b1);
            }
        }
        __syncthreads();
    }

    // epilogue
    float* Cf = (float*)Cv;
    __half* Ch = (__half*)Cv;
#pragma unroll
    for (int i = 0; i < 2; i++) {
        int r0 = brow + wm * 32 + i * 16 + g;
#pragma unroll
        for (int j = 0; j < 8; j++) {
            int col = bcol + wn * 64 + j * 8 + 2 * tig;
            float b0 = __ldg(&bias[col]);
            float b1 = __ldg(&bias[col + 1]);
#pragma unroll
            for (int half_ = 0; half_ < 2; half_++) {
                int r = r0 + half_ * 8;
                if (r >= M) continue;
                float v0 = acc[i][j][2 * half_ + 0] + b0;
                float v1 = acc[i][j][2 * half_ + 1] + b1;
                if (MODE == 1) { v0 = fmaxf(v0, 0.f); v1 = fmaxf(v1, 0.f); }
                if (MODE == 2) {
                    const float2 rr = *reinterpret_cast<const float2*>(&res[(size_t)r * N + col]);
                    v0 += rr.x; v1 += rr.y;
                }
                if (outh) {
                    __half2 hv = __floats2half2_rn(v0, v1);
                    *reinterpret_cast<uint32_t*>(&Ch[(size_t)r * N + col]) = h2u(hv);
                } else {
                    *reinterpret_cast<float2*>(&Cf[(size_t)r * N + col]) = make_float2(v0, v1);
                }
            }
        }
    }
}

template <int MODE, int OUTH>
__global__ __launch_bounds__(256)
void gemm_mma(const __half* __restrict__ A, const __half* __restrict__ Wt,
              const float* __restrict__ bias, const float* __restrict__ res,
              void* __restrict__ Cv, int M, int N, int K) {
    extern __shared__ __half smem[];
    gemm_body<MODE>(A, Wt, bias, res, Cv, M, N, K, OUTH != 0,
                    blockIdx.y * 128, blockIdx.x * 128, smem);
}

// Fused v-proj + oa-proj (independent, same A-rows count, K=256):
// blockIdx.x < 2 -> vh = h(srch @ wtv + bval)   (N=256, fp16 out)
// blockIdx.x >= 2 -> oa = qh @ wtoa + bias_oa   (N=384, f32 out)
__global__ __launch_bounds__(256)
void gemm_fused2(const __half* __restrict__ srch, const __half* __restrict__ qh,
                 const __half* __restrict__ wtv, const __half* __restrict__ wtoa,
                 const float* __restrict__ bval, const float* __restrict__ boa,
                 __half* __restrict__ vh, float* __restrict__ oa, int M) {
    extern __shared__ __half smem[];
    if (blockIdx.x < 2) {
        gemm_body<0>(srch, wtv, bval, nullptr, vh, M, 256, 256, true,
                     blockIdx.y * 128, blockIdx.x * 128, smem);
    } else {
        gemm_body<0>(qh, wtoa, boa, nullptr, oa, M, 384, 256, false,
                     blockIdx.y * 128, (blockIdx.x - 2) * 128, smem);
    }
}

// ---------------------------------------------------------------------------
// Merged weight prep (one launch): all transposes -> fp16 [N,K] + bias concat.
// grid: [0,224) small W tiles | 224 bias | [225,481) W1 | [481,737) W2
// ---------------------------------------------------------------------------
__global__ void prep_weights_k(const float* __restrict__ Wval, const float* __restrict__ Woff,
                               const float* __restrict__ Wattn, const float* __restrict__ Wout,
                               const float* __restrict__ W1, const float* __restrict__ W2,
                               const float* __restrict__ boff, const float* __restrict__ battn,
                               __half* __restrict__ wtv, __half* __restrict__ wtoa,
                               __half* __restrict__ wtO, __half* __restrict__ wt1,
                               __half* __restrict__ wt2, float* __restrict__ bias_oa) {
    __shared__ float t[32][33];
    int blk = blockIdx.x;
    int x = threadIdx.x, y = threadIdx.y;
    if (blk == 224) {
        int tt = y * 32 + x;
        for (int i = tt; i < 384; i += 256)
            bias_oa[i] = (i < 256) ? boff[i] : battn[i - 256];
        return;
    }
    const float* W; __half* Wt; int K, N, lb;
    if (blk < 64)       { W = Wval;  Wt = wtv;              K = 256;  N = 256;  lb = blk; }
    else if (blk < 128) { W = Woff;  Wt = wtoa;             K = 256;  N = 256;  lb = blk - 64; }
    else if (blk < 160) { W = Wattn; Wt = wtoa + 256 * 256; K = 256;  N = 128;  lb = blk - 128; }
    else if (blk < 224) { W = Wout;  Wt = wtO;              K = 256;  N = 256;  lb = blk - 160; }
    else if (blk < 481) { W = W1;    Wt = wt1;              K = 256;  N = 1024; lb = blk - 225; }
    else                { W = W2;    Wt = wt2;              K = 1024; N = 256;  lb = blk - 481; }
    int ntx = N >> 5;
    int n0 = (lb % ntx) * 32, k0 = (lb / ntx) * 32;
#pragma unroll
    for (int i = 0; i < 32; i += 8)
        t[y + i][x] = W[(size_t)(k0 + y + i) * N + n0 + x];
    __syncthreads();
#pragma unroll
    for (int i = 0; i < 32; i += 8)
        Wt[(size_t)(n0 + y + i) * K + k0 + x] = __float2half(t[x][y + i]);
}

// ---------------------------------------------------------------------------
// add: q_h = h(src+pos); src_h = h(src)
// ---------------------------------------------------------------------------
__global__ void add_k(const float4* __restrict__ src4, const float4* __restrict__ pos4,
                      __half* __restrict__ qh, __half* __restrict__ srch, int n4) {
    int i = blockIdx.x * blockDim.x + threadIdx.x;
    if (i >= n4) return;
    float4 s = src4[i], p = pos4[i];
    __half2 q0 = __floats2half2_rn(s.x + p.x, s.y + p.y);
    __half2 q1 = __floats2half2_rn(s.z + p.z, s.w + p.w);
    __half2 s0 = __floats2half2_rn(s.x, s.y);
    __half2 s1 = __floats2half2_rn(s.z, s.w);
    *reinterpret_cast<uint2*>(&qh[(size_t)i * 4])   = make_uint2(h2u(q0), h2u(q1));
    *reinterpret_cast<uint2*>(&srch[(size_t)i * 4]) = make_uint2(h2u(s0), h2u(s1));
}

// ---------------------------------------------------------------------------
// Deformable sampling (fp16 v): one warp per (b,q, head-pair).
// lane = h2(1b) | p(2b) | c8(2b): 2 heads x 4 points x 4 channel-octets.
// Fused softmax over 16 (level,point) logits per head via shuffles.
// ---------------------------------------------------------------------------
__global__ __launch_bounds__(256)
void sample_k(const __half* __restrict__ v, const float* __restrict__ oa,
              const float* __restrict__ ref, __half* __restrict__ out) {
    int warp = (blockIdx.x * blockDim.x + threadIdx.x) >> 5;
    int lane = threadIdx.x & 31;
    if (warp >= MROWS * 4) return;
    int hp  = warp & 3;
    int row = warp >> 2;
    int b   = row / LTOT;
    int h2i = lane >> 4;         // head within pair
    int p   = (lane >> 2) & 3;   // point
    int c8  = lane & 3;          // channel octet (8 halfs)
    int h   = hp * 2 + h2i;

    const int HS[4] = {100, 50, 25, 13};
    const int ST[4] = {0, 10000, 12500, 13125};

    const float* offp = oa + (size_t)row * 384 + h * 32;
    const float* lgp  = oa + (size_t)row * 384 + 256 + h * 16;
    const float* refp = ref + (size_t)row * 8;

    float lg[4];
#pragma unroll
    for (int l = 0; l < 4; l++) lg[l] = __ldg(lgp + l * 4 + p);
    float mx = fmaxf(fmaxf(lg[0], lg[1]), fmaxf(lg[2], lg[3]));
    mx = fmaxf(mx, __shfl_xor_sync(0xffffffffu, mx, 4));
    mx = fmaxf(mx, __shfl_xor_sync(0xffffffffu, mx, 8));
    float e[4], s = 0.f;
#pragma unroll
    for (int l = 0; l < 4; l++) { e[l] = __expf(lg[l] - mx); s += e[l]; }
    s += __shfl_xor_sync(0xffffffffu, s, 4);
    s += __shfl_xor_sync(0xffffffffu, s, 8);
    const float inv = 1.f / s;

    float acc[8];
#pragma unroll
    for (int j = 0; j < 8; j++) acc[j] = 0.f;

#pragma unroll
    for (int l = 0; l < 4; l++) {
        const int H = HS[l], W = HS[l], S = ST[l];
        float rx = __ldg(refp + l * 2 + 0);
        float ry = __ldg(refp + l * 2 + 1);
        float ox = __ldg(offp + l * 8 + p * 2 + 0);
        float oy = __ldg(offp + l * 8 + p * 2 + 1);
        float aww = e[l] * inv;
        float x = rx * (float)W + ox - 0.5f;
        float y = ry * (float)H + oy - 0.5f;
        float x0f = floorf(x), y0f = floorf(y);
        float lx = x - x0f, ly = y - y0f;
        int x0 = (int)x0f, y0 = (int)y0f;
        float w00 = (1.f - lx) * (1.f - ly) * aww;
        float w10 = lx * (1.f - ly) * aww;
        float w01 = (1.f - lx) * ly * aww;
        float w11 = lx * ly * aww;
        bool vx0 = (x0 >= 0) && (x0 < W);
        bool vx1 = (x0 + 1 >= 0) && (x0 + 1 < W);
        bool vy0 = (y0 >= 0) && (y0 < H);
        bool vy1 = (y0 + 1 >= 0) && (y0 + 1 < H);
        // uint4 gather: 8 halfs. index stride = 32 uint4 per spatial pos.
        const uint4* vb = reinterpret_cast<const uint4*>(
            v + (size_t)(b * LTOT + S) * 256) + h * 4 + c8;
#define TAP(widx, cond, wv)                                                   \
        if (cond) {                                                           \
            uint4 t = __ldg(vb + (size_t)(widx) * 32);                        \
            __half2 hh[4];                                                    \
            memcpy(hh, &t, 16);                                               \
            _Pragma("unroll")                                                 \
            for (int j = 0; j < 4; j++) {                                     \
                float2 f = __half22float2(hh[j]);                             \
                acc[2 * j]     += (wv) * f.x;                                 \
                acc[2 * j + 1] += (wv) * f.y;                                 \
            }                                                                 \
        }
        TAP(y0 * W + x0,           vy0 && vx0, w00)
        TAP(y0 * W + x0 + 1,       vy0 && vx1, w10)
        TAP((y0 + 1) * W + x0,     vy1 && vx0, w01)
        TAP((y0 + 1) * W + x0 + 1, vy1 && vx1, w11)
#undef TAP
    }
    // reduce over point (lane bits 2,3)
#pragma unroll
    for (int j = 0; j < 8; j++) {
        acc[j] += __shfl_xor_sync(0xffffffffu, acc[j], 4);
        acc[j] += __shfl_xor_sync(0xffffffffu, acc[j], 8);
    }
    if (p == 0) {
        uint4 pk = make_uint4(h2u(__floats2half2_rn(acc[0], acc[1])),
                              h2u(__floats2half2_rn(acc[2], acc[3])),
                              h2u(__floats2half2_rn(acc[4], acc[5])),
                              h2u(__floats2half2_rn(acc[6], acc[7])));
        *reinterpret_cast<uint4*>(&out[(size_t)row * DMODEL + h * DHEAD + c8 * 8]) = pk;
    }
}

// ---------------------------------------------------------------------------
// LayerNorm over 256; optional fp16 copy
// ---------------------------------------------------------------------------
__global__ __launch_bounds__(256)
void ln_k(const float* __restrict__ in, const float* __restrict__ g,
          const float* __restrict__ b, float* __restrict__ out,
          __half* __restrict__ out_h) {
    int row = blockIdx.x;
    int t = threadIdx.x;
    float v = in[(size_t)row * DMODEL + t];
    float s = v, s2 = v * v;
#pragma unroll
    for (int o = 16; o > 0; o >>= 1) {
        s  += __shfl_xor_sync(0xffffffff, s,  o);
        s2 += __shfl_xor_sync(0xffffffff, s2, o);
    }
    __shared__ float sh[8], sh2[8];
    int wid = t >> 5, lane = t & 31;
    if (lane == 0) { sh[wid] = s; sh2[wid] = s2; }
    __syncthreads();
    float ts = 0.f, ts2 = 0.f;
#pragma unroll
    for (int i = 0; i < 8; i++) { ts += sh[i]; ts2 += sh2[i]; }
    float mu = ts * (1.f / DMODEL);
    float var = ts2 * (1.f / DMODEL) - mu * mu;
    float inv = rsqrtf(var + 1e-5f);
    float r = (v - mu) * inv * g[t] + b[t];
    out[(size_t)row * DMODEL + t] = r;
    if (out_h) out_h[(size_t)row * DMODEL + t] = __float2half(r);
}

// ---------------------------------------------------------------------------
// Launch
// ---------------------------------------------------------------------------
extern "C" void kernel_launch(void* const* d_in, const int* in_sizes, int n_in,
                              void* d_out, int out_size) {
    const float* src   = (const float*)d_in[0];
    const float* pos   = (const float*)d_in[1];
    const float* ref   = (const float*)d_in[2];
    const float* Woff  = (const float*)d_in[5];
    const float* boff  = (const float*)d_in[6];
    const float* Wattn = (const float*)d_in[7];
    const float* battn = (const float*)d_in[8];
    const float* Wval  = (const float*)d_in[9];
    const float* bval  = (const float*)d_in[10];
    const float* Wout  = (const float*)d_in[11];
    const float* bout  = (const float*)d_in[12];
    const float* lsg   = (const float*)d_in[13];
    const float* lsb   = (const float*)d_in[14];
    const float* W1    = (const float*)d_in[15];
    const float* b1    = (const float*)d_in[16];
    const float* W2    = (const float*)d_in[17];
    const float* b2    = (const float*)d_in[18];
    const float* lfg   = (const float*)d_in[19];
    const float* lfb   = (const float*)d_in[20];
    float* out = (float*)d_out;

    __half *srch, *qh, *vh, *samph, *xh, *h1h;
    __half *wtv, *wtoa, *wtO, *wt1, *wt2;
    float *oa, *tmp, *x, *boa;
    cudaGetSymbolAddress((void**)&srch,  g_src_h);
    cudaGetSymbolAddress((void**)&qh,    g_q_h);
    cudaGetSymbolAddress((void**)&vh,    g_v_h);
    cudaGetSymbolAddress((void**)&oa,    g_oa);
    cudaGetSymbolAddress((void**)&samph, g_samp_h);
    cudaGetSymbolAddress((void**)&tmp,   g_tmp);
    cudaGetSymbolAddress((void**)&x,     g_x);
    cudaGetSymbolAddress((void**)&xh,    g_x_h);
    cudaGetSymbolAddress((void**)&h1h,   g_h1_h);
    cudaGetSymbolAddress((void**)&wtv,   g_wt_val);
    cudaGetSymbolAddress((void**)&wtoa,  g_wt_oa);
    cudaGetSymbolAddress((void**)&wtO,   g_wt_out);
    cudaGetSymbolAddress((void**)&wt1,   g_wt_1);
    cudaGetSymbolAddress((void**)&wt2,   g_wt_2);
    cudaGetSymbolAddress((void**)&boa,   g_bias_oa);

    cudaFuncSetAttribute(gemm_fused2,   cudaFuncAttributeMaxDynamicSharedMemorySize, GEMM_SMEM);
    cudaFuncSetAttribute(gemm_mma<1,1>, cudaFuncAttributeMaxDynamicSharedMemorySize, GEMM_SMEM);
    cudaFuncSetAttribute(gemm_mma<2,0>, cudaFuncAttributeMaxDynamicSharedMemorySize, GEMM_SMEM);

    const int M = MROWS;
    const int mblk = (M + 127) / 128;   // 416
    dim3 tb(32, 8);

    // 1. all weight transposes + bias concat in ONE launch
    prep_weights_k<<<737, tb>>>(Wval, Woff, Wattn, Wout, W1, W2, boff, battn,
                                wtv, wtoa, wtO, wt1, wt2, boa);
    // 2. q_h = h(src+pos); src_h = h(src)
    {
        int n4 = M * DMODEL / 4;
        add_k<<<(n4 + 255) / 256, 256>>>((const float4*)src, (const float4*)pos,
                                         qh, srch, n4);
    }
    // 3. fused: vh = h(srch @ Wval + bval)  AND  oa = qh @ [Woff|Wattn] + boa
    gemm_fused2<<<dim3(5, mblk), 256, GEMM_SMEM>>>(srch, qh, wtv, wtoa,
                                                   bval, boa, vh, oa, M);
    // 4. sampling + fused softmax -> samp_h
    sample_k<<<(M * 4 + 7) / 8, 256>>>(vh, oa, ref, samph);
    // 5. tmp = samp_h @ Wout + bout + src (f32)
    gemm_mma<2,0><<<dim3(2, mblk), 256, GEMM_SMEM>>>(samph, wtO, bout, src, tmp, M, 256, 256);
    // 6. x = LN(tmp), x_h copy
    ln_k<<<M, 256>>>(tmp, lsg, lsb, x, xh);
    // 7. h1_h = relu(x_h @ W1 + b1)  (fp16 out)
    gemm_mma<1,1><<<dim3(8, mblk), 256, GEMM_SMEM>>>(xh, wt1, b1, nullptr, h1h, M, 1024, 256);
    // 8. tmp = h1_h @ W2 + b2 + x  (f32)
    gemm_mma<2,0><<<dim3(2, mblk), 256, GEMM_SMEM>>>(h1h, wt2, b2, x, tmp, M, 256, 1024);
    // 9. out = LN(tmp)
    ln_k<<<M, 256>>>(tmp, lfg, lfb, out, nullptr);
}

// round 17
// speedup vs baseline: 1.5682x; 1.0597x over previous
#include <cuda_runtime.h>
#include <cuda_fp16.h>
#include <cstdint>
#include <cstring>

// ---------------------------------------------------------------------------
// Problem constants
// ---------------------------------------------------------------------------
#define BATCH 4
#define LTOT  13294
#define MROWS (BATCH * LTOT)   // 53176
#define DMODEL 256
#define DFFN   1024
#define NHEAD  8
#define NLVL   4
#define NPTS   4
#define DHEAD  32

// ---------------------------------------------------------------------------
// Scratch (device globals)
// ---------------------------------------------------------------------------
__device__ __half g_src_h[MROWS * DMODEL];
__device__ __half g_q_h  [MROWS * DMODEL];
__device__ __half g_v_h  [MROWS * DMODEL];
__device__ float  g_oa   [MROWS * 384];     // offsets(256) + attn logits(128), f32
__device__ __half g_samp_h[MROWS * DMODEL];
__device__ float  g_tmp  [MROWS * DMODEL];
__device__ float  g_x    [MROWS * DMODEL];
__device__ __half g_x_h  [MROWS * DMODEL];
__device__ __half g_h1_h [MROWS * DFFN];
// transposed weights [N, K] fp16
__device__ __half g_wt_val[DMODEL * DMODEL];
__device__ __half g_wt_oa [384 * DMODEL];
__device__ __half g_wt_out[DMODEL * DMODEL];
__device__ __half g_wt_1  [DFFN * DMODEL];
__device__ __half g_wt_2  [DMODEL * DFFN];
__device__ float  g_bias_oa[384];

// ---------------------------------------------------------------------------
// Helpers
// ---------------------------------------------------------------------------
__device__ __forceinline__ uint32_t h2u(__half2 v) {
    uint32_t r;
    memcpy(&r, &v, 4);
    return r;
}

__device__ __forceinline__ void mma_16n8k16(float* d, const uint32_t* a, const uint32_t* b) {
    asm volatile(
        "mma.sync.aligned.m16n8k16.row.col.f32.f16.f16.f32 "
        "{%0,%1,%2,%3}, {%4,%5,%6,%7}, {%8,%9}, {%0,%1,%2,%3};"
        : "+f"(d[0]), "+f"(d[1]), "+f"(d[2]), "+f"(d[3])
        : "r"(a[0]), "r"(a[1]), "r"(a[2]), "r"(a[3]), "r"(b[0]), "r"(b[1]));
}

#define LDSM_X4(r0, r1, r2, r3, addr) \
    asm volatile("ldmatrix.sync.aligned.m8n8.x4.shared.b16 {%0,%1,%2,%3}, [%4];" \
        : "=r"(r0), "=r"(r1), "=r"(r2), "=r"(r3) : "r"(addr))

#define CP_ASYNC16(dst, src, nbytes) \
    asm volatile("cp.async.cg.shared.global [%0], [%1], 16, %2;" \
        :: "r"(dst), "l"(src), "r"(nbytes))
#define CP_COMMIT() asm volatile("cp.async.commit_group;")
#define CP_WAIT1()  asm volatile("cp.async.wait_group 1;")
#define CP_WAIT0()  asm volatile("cp.async.wait_group 0;")

// ---------------------------------------------------------------------------
// fp16 mma.sync GEMM body (R10 config: 3-stage cp.async, ldmatrix, BK=32).
// 128x128 CTA tile, 8 warps of 32x64, m16n8k16.
// MODE: 0 = bias, 1 = bias+relu, 2 = bias+residual(f32)
// ---------------------------------------------------------------------------
#define LDSH 40                          // padded smem row stride (halfs) = 80B
#define TILE_H (128 * LDSH)              // halfs per tile buffer
#define TILE_BYTES (TILE_H * 2)          // 10240
#define GEMM_SMEM (6 * TILE_BYTES)       // 61440 bytes (A0..2, B0..2)

template <int MODE>
__device__ __forceinline__
void gemm_body(const __half* __restrict__ A, const __half* __restrict__ Wt,
               const float* __restrict__ bias, const float* __restrict__ res,
               void* __restrict__ Cv, int M, int N, int K,
               bool outh, int brow, int bcol, __half* smem) {
    __half* sAbase = smem;                 // 3 tiles
    __half* sBbase = smem + 3 * TILE_H;    // 3 tiles

    const int tid  = threadIdx.x;
    const int wid  = tid >> 5;
    const int lane = tid & 31;
    const int g    = lane >> 2;      // groupID 0..7
    const int tig  = lane & 3;       // thread-in-group 0..3
    const int wm   = wid >> 1;       // 0..3 (32-row slab)
    const int wn   = wid & 1;        // 0..1 (64-col slab)
    const int NC   = K >> 5;

    // cp.async loader: 2 segments per thread per matrix (512 x 16B per tile)
    const int r0l = tid >> 2;          // rows 0..63
    const int seg = tid & 3;           // 16B segment within 64B row
    uint32_t cpA[2], cpB[2];
#pragma unroll
    for (int i = 0; i < 2; i++) {
        cpA[i] = (uint32_t)__cvta_generic_to_shared(&sAbase[(r0l + i * 64) * LDSH + seg * 8]);
        cpB[i] = (uint32_t)__cvta_generic_to_shared(&sBbase[(r0l + i * 64) * LDSH + seg * 8]);
    }

    // ldmatrix offsets (bytes, relative to tile base; +32B per k-step of 16)
    uint32_t aAddr0 = (uint32_t)__cvta_generic_to_shared(sAbase);
    uint32_t bAddr0 = (uint32_t)__cvta_generic_to_shared(sBbase);
    uint32_t aoff[2];
#pragma unroll
    for (int i = 0; i < 2; i++)
        aoff[i] = (uint32_t)(((wm * 32 + i * 16 + (lane & 15)) * LDSH + ((lane >> 4) << 3)) * 2);
    uint32_t boff[4];
#pragma unroll
    for (int j4 = 0; j4 < 4; j4++)
        boff[j4] = (uint32_t)(((wn * 64 + j4 * 16 + (lane & 7) + ((lane >> 4) << 3)) * LDSH
                               + (((lane >> 3) & 1) << 3)) * 2);

    float acc[2][8][4];
#pragma unroll
    for (int i = 0; i < 2; i++)
#pragma unroll
        for (int j = 0; j < 8; j++)
#pragma unroll
            for (int t = 0; t < 4; t++) acc[i][j][t] = 0.f;

    auto issue = [&](int ck) {
        const uint32_t bo = (uint32_t)(ck % 3) * TILE_BYTES;
        const int k0 = ck << 5;
#pragma unroll
        for (int i = 0; i < 2; i++) {
            int row = r0l + i * 64;
            CP_ASYNC16(cpA[i] + bo, &A[(size_t)(brow + row) * K + k0 + seg * 8],
                       (brow + row < M) ? 16 : 0);
            CP_ASYNC16(cpB[i] + bo, &Wt[(size_t)(bcol + row) * K + k0 + seg * 8], 16);
        }
        CP_COMMIT();
    };

    issue(0);
    if (NC > 1) issue(1);
    for (int c = 0; c < NC; ++c) {
        if (c + 1 < NC) CP_WAIT1(); else CP_WAIT0();
        __syncthreads();
        if (c + 2 < NC) issue(c + 2);

        const uint32_t tb = (uint32_t)(c % 3) * TILE_BYTES;
        const uint32_t aB = aAddr0 + tb;
        const uint32_t bB = bAddr0 + tb;
#pragma unroll
        for (int s = 0; s < 2; s++) {           // two K=16 steps per chunk
            const uint32_t ks = (uint32_t)(s * 32);  // 16 halfs = 32B
            uint32_t afr[2][4];
#pragma unroll
            for (int i = 0; i < 2; i++)
                LDSM_X4(afr[i][0], afr[i][1], afr[i][2], afr[i][3], aB + aoff[i] + ks);
#pragma unroll
            for (int j4 = 0; j4 < 4; j4++) {
                uint32_t b0[2], b1[2];
                LDSM_X4(b0[0], b0[1], b1[0], b1[1], bB + boff[j4] + ks);
                mma_16n8k16(acc[0][2 * j4 + 0], afr[0], b0);
                mma_16n8k16(acc[1][2 * j4 + 0], afr[1], b0);
                mma_16n8k16(acc[0][2 * j4 + 1], afr[0], b1);
                mma_16n8k16(acc[1][2 * j4 + 1], afr[1], b1);
            }
        }
        __syncthreads();
    }

    // epilogue
    float* Cf = (float*)Cv;
    __half* Ch = (__half*)Cv;
#pragma unroll
    for (int i = 0; i < 2; i++) {
        int r0 = brow + wm * 32 + i * 16 + g;
#pragma unroll
        for (int j = 0; j < 8; j++) {
            int col = bcol + wn * 64 + j * 8 + 2 * tig;
            float b0 = __ldg(&bias[col]);
            float b1 = __ldg(&bias[col + 1]);
#pragma unroll
            for (int half_ = 0; half_ < 2; half_++) {
                int r = r0 + half_ * 8;
                if (r >= M) continue;
                float v0 = acc[i][j][2 * half_ + 0] + b0;
                float v1 = acc[i][j][2 * half_ + 1] + b1;
                if (MODE == 1) { v0 = fmaxf(v0, 0.f); v1 = fmaxf(v1, 0.f); }
                if (MODE == 2) {
                    const float2 rr = *reinterpret_cast<const float2*>(&res[(size_t)r * N + col]);
                    v0 += rr.x; v1 += rr.y;
                }
                if (outh) {
                    __half2 hv = __floats2half2_rn(v0, v1);
                    *reinterpret_cast<uint32_t*>(&Ch[(size_t)r * N + col]) = h2u(hv);
                } else {
                    *reinterpret_cast<float2*>(&Cf[(size_t)r * N + col]) = make_float2(v0, v1);
                }
            }
        }
    }
}

template <int MODE, int OUTH>
__global__ __launch_bounds__(256)
void gemm_mma(const __half* __restrict__ A, const __half* __restrict__ Wt,
              const float* __restrict__ bias, const float* __restrict__ res,
              void* __restrict__ Cv, int M, int N, int K) {
    extern __shared__ __half smem[];
    gemm_body<MODE>(A, Wt, bias, res, Cv, M, N, K, OUTH != 0,
                    blockIdx.y * 128, blockIdx.x * 128, smem);
}

// Fused v-proj + oa-proj (independent, same A-rows count, K=256):
__global__ __launch_bounds__(256)
void gemm_fused2(const __half* __restrict__ srch, const __half* __restrict__ qh,
                 const __half* __restrict__ wtv, const __half* __restrict__ wtoa,
                 const float* __restrict__ bval, const float* __restrict__ boa,
                 __half* __restrict__ vh, float* __restrict__ oa, int M) {
    extern __shared__ __half smem[];
    if (blockIdx.x < 2) {
        gemm_body<0>(srch, wtv, bval, nullptr, vh, M, 256, 256, true,
                     blockIdx.y * 128, blockIdx.x * 128, smem);
    } else {
        gemm_body<0>(qh, wtoa, boa, nullptr, oa, M, 384, 256, false,
                     blockIdx.y * 128, (blockIdx.x - 2) * 128, smem);
    }
}

// ---------------------------------------------------------------------------
// Merged weight prep (one launch): all transposes -> fp16 [N,K] + bias concat.
// ---------------------------------------------------------------------------
__global__ void prep_weights_k(const float* __restrict__ Wval, const float* __restrict__ Woff,
                               const float* __restrict__ Wattn, const float* __restrict__ Wout,
                               const float* __restrict__ W1, const float* __restrict__ W2,
                               const float* __restrict__ boff, const float* __restrict__ battn,
                               __half* __restrict__ wtv, __half* __restrict__ wtoa,
                               __half* __restrict__ wtO, __half* __restrict__ wt1,
                               __half* __restrict__ wt2, float* __restrict__ bias_oa) {
    __shared__ float t[32][33];
    int blk = blockIdx.x;
    int x = threadIdx.x, y = threadIdx.y;
    if (blk == 224) {
        int tt = y * 32 + x;
        for (int i = tt; i < 384; i += 256)
            bias_oa[i] = (i < 256) ? boff[i] : battn[i - 256];
        return;
    }
    const float* W; __half* Wt; int K, N, lb;
    if (blk < 64)       { W = Wval;  Wt = wtv;              K = 256;  N = 256;  lb = blk; }
    else if (blk < 128) { W = Woff;  Wt = wtoa;             K = 256;  N = 256;  lb = blk - 64; }
    else if (blk < 160) { W = Wattn; Wt = wtoa + 256 * 256; K = 256;  N = 128;  lb = blk - 128; }
    else if (blk < 224) { W = Wout;  Wt = wtO;              K = 256;  N = 256;  lb = blk - 160; }
    else if (blk < 481) { W = W1;    Wt = wt1;              K = 256;  N = 1024; lb = blk - 225; }
    else                { W = W2;    Wt = wt2;              K = 1024; N = 256;  lb = blk - 481; }
    int ntx = N >> 5;
    int n0 = (lb % ntx) * 32, k0 = (lb / ntx) * 32;
#pragma unroll
    for (int i = 0; i < 32; i += 8)
        t[y + i][x] = W[(size_t)(k0 + y + i) * N + n0 + x];
    __syncthreads();
#pragma unroll
    for (int i = 0; i < 32; i += 8)
        Wt[(size_t)(n0 + y + i) * K + k0 + x] = __float2half(t[x][y + i]);
}

// ---------------------------------------------------------------------------
// add: q_h = h(src+pos); src_h = h(src)
// ---------------------------------------------------------------------------
__global__ void add_k(const float4* __restrict__ src4, const float4* __restrict__ pos4,
                      __half* __restrict__ qh, __half* __restrict__ srch, int n4) {
    int i = blockIdx.x * blockDim.x + threadIdx.x;
    if (i >= n4) return;
    float4 s = src4[i], p = pos4[i];
    __half2 q0 = __floats2half2_rn(s.x + p.x, s.y + p.y);
    __half2 q1 = __floats2half2_rn(s.z + p.z, s.w + p.w);
    __half2 s0 = __floats2half2_rn(s.x, s.y);
    __half2 s1 = __floats2half2_rn(s.z, s.w);
    *reinterpret_cast<uint2*>(&qh[(size_t)i * 4])   = make_uint2(h2u(q0), h2u(q1));
    *reinterpret_cast<uint2*>(&srch[(size_t)i * 4]) = make_uint2(h2u(s0), h2u(s1));
}

// ---------------------------------------------------------------------------
// Deformable sampling (fp16 v, fp16 HFMA2 accumulation): one warp per
// (b,q, head-pair). lane = h2(1b) | p(2b) | c8(2b).
// Fused softmax over 16 (level,point) logits per head via shuffles.
// ---------------------------------------------------------------------------
__global__ __launch_bounds__(256)
void sample_k(const __half* __restrict__ v, const float* __restrict__ oa,
              const float* __restrict__ ref, __half* __restrict__ out) {
    int warp = (blockIdx.x * blockDim.x + threadIdx.x) >> 5;
    int lane = threadIdx.x & 31;
    if (warp >= MROWS * 4) return;
    int hp  = warp & 3;
    int row = warp >> 2;
    int b   = row / LTOT;
    int h2i = lane >> 4;         // head within pair
    int p   = (lane >> 2) & 3;   // point
    int c8  = lane & 3;          // channel octet (8 halfs)
    int h   = hp * 2 + h2i;

    const int HS[4] = {100, 50, 25, 13};
    const int ST[4] = {0, 10000, 12500, 13125};

    const float* offp = oa + (size_t)row * 384 + h * 32;
    const float* lgp  = oa + (size_t)row * 384 + 256 + h * 16;
    const float* refp = ref + (size_t)row * 8;

    float lg[4];
#pragma unroll
    for (int l = 0; l < 4; l++) lg[l] = __ldg(lgp + l * 4 + p);
    float mx = fmaxf(fmaxf(lg[0], lg[1]), fmaxf(lg[2], lg[3]));
    mx = fmaxf(mx, __shfl_xor_sync(0xffffffffu, mx, 4));
    mx = fmaxf(mx, __shfl_xor_sync(0xffffffffu, mx, 8));
    float e[4], s = 0.f;
#pragma unroll
    for (int l = 0; l < 4; l++) { e[l] = __expf(lg[l] - mx); s += e[l]; }
    s += __shfl_xor_sync(0xffffffffu, s, 4);
    s += __shfl_xor_sync(0xffffffffu, s, 8);
    const float inv = 1.f / s;

    __half2 acc2[4];
#pragma unroll
    for (int j = 0; j < 4; j++) acc2[j] = __float2half2_rn(0.f);

#pragma unroll
    for (int l = 0; l < 4; l++) {
        const int H = HS[l], W = HS[l], S = ST[l];
        float rx = __ldg(refp + l * 2 + 0);
        float ry = __ldg(refp + l * 2 + 1);
        float ox = __ldg(offp + l * 8 + p * 2 + 0);
        float oy = __ldg(offp + l * 8 + p * 2 + 1);
        float aww = e[l] * inv;
        float x = rx * (float)W + ox - 0.5f;
        float y = ry * (float)H + oy - 0.5f;
        float x0f = floorf(x), y0f = floorf(y);
        float lx = x - x0f, ly = y - y0f;
        int x0 = (int)x0f, y0 = (int)y0f;
        float w00 = (1.f - lx) * (1.f - ly) * aww;
        float w10 = lx * (1.f - ly) * aww;
        float w01 = (1.f - lx) * ly * aww;
        float w11 = lx * ly * aww;
        bool vx0 = (x0 >= 0) && (x0 < W);
        bool vx1 = (x0 + 1 >= 0) && (x0 + 1 < W);
        bool vy0 = (y0 >= 0) && (y0 < H);
        bool vy1 = (y0 + 1 >= 0) && (y0 + 1 < H);
        // uint4 gather: 8 halfs. index stride = 32 uint4 per spatial pos.
        const uint4* vb = reinterpret_cast<const uint4*>(
            v + (size_t)(b * LTOT + S) * 256) + h * 4 + c8;
#define TAP(widx, cond, wv)                                                   \
        if (cond) {                                                           \
            uint4 t = __ldg(vb + (size_t)(widx) * 32);                        \
            __half2 wv2 = __float2half2_rn(wv);                               \
            __half2 hh[4];                                                    \
            memcpy(hh, &t, 16);                                               \
            acc2[0] = __hfma2(wv2, hh[0], acc2[0]);                           \
            acc2[1] = __hfma2(wv2, hh[1], acc2[1]);                           \
            acc2[2] = __hfma2(wv2, hh[2], acc2[2]);                           \
            acc2[3] = __hfma2(wv2, hh[3], acc2[3]);                           \
        }
        TAP(y0 * W + x0,           vy0 && vx0, w00)
        TAP(y0 * W + x0 + 1,       vy0 && vx1, w10)
        TAP((y0 + 1) * W + x0,     vy1 && vx0, w01)
        TAP((y0 + 1) * W + x0 + 1, vy1 && vx1, w11)
#undef TAP
    }
    // convert to fp32 and reduce over point (lane bits 2,3)
    float acc[8];
#pragma unroll
    for (int j = 0; j < 4; j++) {
        float2 f = __half22float2(acc2[j]);
        acc[2 * j] = f.x; acc[2 * j + 1] = f.y;
    }
#pragma unroll
    for (int j = 0; j < 8; j++) {
        acc[j] += __shfl_xor_sync(0xffffffffu, acc[j], 4);
        acc[j] += __shfl_xor_sync(0xffffffffu, acc[j], 8);
    }
    if (p == 0) {
        uint4 pk = make_uint4(h2u(__floats2half2_rn(acc[0], acc[1])),
                              h2u(__floats2half2_rn(acc[2], acc[3])),
                              h2u(__floats2half2_rn(acc[4], acc[5])),
                              h2u(__floats2half2_rn(acc[6], acc[7])));
        *reinterpret_cast<uint4*>(&out[(size_t)row * DMODEL + h * DHEAD + c8 * 8]) = pk;
    }
}

// ---------------------------------------------------------------------------
// LayerNorm over 256; optional fp16 copy
// ---------------------------------------------------------------------------
__global__ __launch_bounds__(256)
void ln_k(const float* __restrict__ in, const float* __restrict__ g,
          const float* __restrict__ b, float* __restrict__ out,
          __half* __restrict__ out_h) {
    int row = blockIdx.x;
    int t = threadIdx.x;
    float v = in[(size_t)row * DMODEL + t];
    float s = v, s2 = v * v;
#pragma unroll
    for (int o = 16; o > 0; o >>= 1) {
        s  += __shfl_xor_sync(0xffffffff, s,  o);
        s2 += __shfl_xor_sync(0xffffffff, s2, o);
    }
    __shared__ float sh[8], sh2[8];
    int wid = t >> 5, lane = t & 31;
    if (lane == 0) { sh[wid] = s; sh2[wid] = s2; }
    __syncthreads();
    float ts = 0.f, ts2 = 0.f;
#pragma unroll
    for (int i = 0; i < 8; i++) { ts += sh[i]; ts2 += sh2[i]; }
    float mu = ts * (1.f / DMODEL);
    float var = ts2 * (1.f / DMODEL) - mu * mu;
    float inv = rsqrtf(var + 1e-5f);
    float r = (v - mu) * inv * g[t] + b[t];
    out[(size_t)row * DMODEL + t] = r;
    if (out_h) out_h[(size_t)row * DMODEL + t] = __float2half(r);
}

// ---------------------------------------------------------------------------
// Launch
// ---------------------------------------------------------------------------
extern "C" void kernel_launch(void* const* d_in, const int* in_sizes, int n_in,
                              void* d_out, int out_size) {
    const float* src   = (const float*)d_in[0];
    const float* pos   = (const float*)d_in[1];
    const float* ref   = (const float*)d_in[2];
    const float* Woff  = (const float*)d_in[5];
    const float* boff  = (const float*)d_in[6];
    const float* Wattn = (const float*)d_in[7];
    const float* battn = (const float*)d_in[8];
    const float* Wval  = (const float*)d_in[9];
    const float* bval  = (const float*)d_in[10];
    const float* Wout  = (const float*)d_in[11];
    const float* bout  = (const float*)d_in[12];
    const float* lsg   = (const float*)d_in[13];
    const float* lsb   = (const float*)d_in[14];
    const float* W1    = (const float*)d_in[15];
    const float* b1    = (const float*)d_in[16];
    const float* W2    = (const float*)d_in[17];
    const float* b2    = (const float*)d_in[18];
    const float* lfg   = (const float*)d_in[19];
    const float* lfb   = (const float*)d_in[20];
    float* out = (float*)d_out;

    __half *srch, *qh, *vh, *samph, *xh, *h1h;
    __half *wtv, *wtoa, *wtO, *wt1, *wt2;
    float *oa, *tmp, *x, *boa;
    cudaGetSymbolAddress((void**)&srch,  g_src_h);
    cudaGetSymbolAddress((void**)&qh,    g_q_h);
    cudaGetSymbolAddress((void**)&vh,    g_v_h);
    cudaGetSymbolAddress((void**)&oa,    g_oa);
    cudaGetSymbolAddress((void**)&samph, g_samp_h);
    cudaGetSymbolAddress((void**)&tmp,   g_tmp);
    cudaGetSymbolAddress((void**)&x,     g_x);
    cudaGetSymbolAddress((void**)&xh,    g_x_h);
    cudaGetSymbolAddress((void**)&h1h,   g_h1_h);
    cudaGetSymbolAddress((void**)&wtv,   g_wt_val);
    cudaGetSymbolAddress((void**)&wtoa,  g_wt_oa);
    cudaGetSymbolAddress((void**)&wtO,   g_wt_out);
    cudaGetSymbolAddress((void**)&wt1,   g_wt_1);
    cudaGetSymbolAddress((void**)&wt2,   g_wt_2);
    cudaGetSymbolAddress((void**)&boa,   g_bias_oa);

    cudaFuncSetAttribute(gemm_fused2,   cudaFuncAttributeMaxDynamicSharedMemorySize, GEMM_SMEM);
    cudaFuncSetAttribute(gemm_mma<1,1>, cudaFuncAttributeMaxDynamicSharedMemorySize, GEMM_SMEM);
    cudaFuncSetAttribute(gemm_mma<2,0>, cudaFuncAttributeMaxDynamicSharedMemorySize, GEMM_SMEM);

    const int M = MROWS;
    const int mblk = (M + 127) / 128;   // 416
    dim3 tb(32, 8);

    // 1. all weight transposes + bias concat in ONE launch
    prep_weights_k<<<737, tb>>>(Wval, Woff, Wattn, Wout, W1, W2, boff, battn,
                                wtv, wtoa, wtO, wt1, wt2, boa);
    // 2. q_h = h(src+pos); src_h = h(src)
    {
        int n4 = M * DMODEL / 4;
        add_k<<<(n4 + 255) / 256, 256>>>((const float4*)src, (const float4*)pos,
                                         qh, srch, n4);
    }
    // 3. fused: vh = h(srch @ Wval + bval)  AND  oa = qh @ [Woff|Wattn] + boa
    gemm_fused2<<<dim3(5, mblk), 256, GEMM_SMEM>>>(srch, qh, wtv, wtoa,
                                                   bval, boa, vh, oa, M);
    // 4. sampling + fused softmax -> samp_h
    sample_k<<<(M * 4 + 7) / 8, 256>>>(vh, oa, ref, samph);
    // 5. tmp = samp_h @ Wout + bout + src (f32)
    gemm_mma<2,0><<<dim3(2, mblk), 256, GEMM_SMEM>>>(samph, wtO, bout, src, tmp, M, 256, 256);
    // 6. x = LN(tmp), x_h copy
    ln_k<<<M, 256>>>(tmp, lsg, lsb, x, xh);
    // 7. h1_h = relu(x_h @ W1 + b1)  (fp16 out)
    gemm_mma<1,1><<<dim3(8, mblk), 256, GEMM_SMEM>>>(xh, wt1, b1, nullptr, h1h, M, 1024, 256);
    // 8. tmp = h1_h @ W2 + b2 + x  (f32)
    gemm_mma<2,0><<<dim3(2, mblk), 256, GEMM_SMEM>>>(h1h, wt2, b2, x, tmp, M, 256, 1024);
    // 9. out = LN(tmp)
    ln_k<<<M, 256>>>(tmp, lfg, lfb, out, nullptr);
}